// round 4
// baseline (speedup 1.0000x reference)
#include <cuda_runtime.h>

typedef unsigned long long u64;

#define NSC 5
#define CO_T 64
#define CI_CH 8
#define THREADS 256
#define ACT_NSTR 5586944LL   // per-n elements in activation buffer (256 * 21824)
#define ACT_N    11173888LL  // per-head elements (n = 2)
#define ANCH_TOT 196416LL    // sum(H*W*9)

// Ping-pong activation scratch: [head][n*ACT_NSTR + scale_off + c*H*W + y*W + x]
__device__ float g_actA[2][11173888];
__device__ float g_actB[2][11173888];

struct KArgs {
    const float* inP[10];        // [head*5 + scale], base for n=0
    const float* wP[2];          // per-head weights [Cout][256][3][3]
    const float* bP[2];          // per-head bias
    float*       outP[2];        // MAIN: per-head act base; else: d_out region
    long long    inNStr[NSC];    // per-scale n-stride (elements)
    long long    outOff[NSC];    // MAIN: act scale offsets; else: anchor-position base per scale
    int Hs[NSC], Ws[NSC], tXs[NSC];
    int tStart[NSC + 1];
    int cOut;                    // 256 / 819 / 36
    int kk;                      // classes-per-anchor (91 / 4); unused in MAIN
};

__device__ __forceinline__ u64 dupf(float x) {
    u64 r; asm("mov.b64 %0, {%1, %1};" : "=l"(r) : "f"(x)); return r;
}
__device__ __forceinline__ u64 packf(float lo, float hi) {
    u64 r; asm("mov.b64 %0, {%1, %2};" : "=l"(r) : "f"(lo), "f"(hi)); return r;
}
__device__ __forceinline__ void unpackf(u64 v, float& lo, float& hi) {
    asm("mov.b64 {%0, %1}, %2;" : "=f"(lo), "=f"(hi) : "l"(v));
}
// packed dual-FMA: 2 fp32 FMAs per instruction (sm_100+)
__device__ __forceinline__ void fma2(u64& a, u64 w, u64 x) {
    asm("fma.rn.f32x2 %0, %1, %2, %0;" : "+l"(a) : "l"(w), "l"(x));
}

// One block: 64 output channels x (8 rows x 16 cols) spatial tile.
// Thread tile: 8 co (4 f32x2 pairs) x 4 consecutive cols.
// K-loop: 32 chunks of 8 input channels staged through shared memory.
template<int MAIN>
__global__ __launch_bounds__(THREADS, 2)
void conv3x3_k(KArgs A)
{
    __shared__ __align__(16) float in_s[CI_CH * 10 * 19];   // halo 10x18, row stride 19 (bank-friendly)
    __shared__ __align__(16) float w_s[CI_CH * 9 * CO_T];   // [ci][tap][co]

    // scale lookup from linear spatial-tile id
    int bt = blockIdx.x;
    int s = 0;
#pragma unroll
    for (int i = 1; i < NSC; i++) if (bt >= A.tStart[i]) s = i;
    int local = bt - A.tStart[s];
    int H = A.Hs[s], W = A.Ws[s], tX = A.tXs[s];
    int tileX = local % tX, tileY = local / tX;

    int z = blockIdx.z;
    int head = MAIN ? (z >> 1) : 0;
    int n    = MAIN ? (z & 1)  : z;
    int cb   = blockIdx.y;

    const float* inB = A.inP[head * NSC + s] + (long long)n * A.inNStr[s];
    const float* wB  = A.wP[head];
    const float* bB  = A.bP[head];

    int tid = threadIdx.x;
    int spg = tid & 31, tyg = tid >> 5;          // warp = 32 spatial groups, fixed co-group
    int rL  = spg >> 2, cg = spg & 3, cL = cg * 4;
    int y0 = tileY * 8, x0 = tileX * 16;
    int y = y0 + rL, x = x0 + cL;
    bool colOk = (x < W);                        // W multiple of 4; all-or-nothing per 4-col group
    int coBase = cb * CO_T + tyg * 8;

    u64 acc[4][4];
#pragma unroll
    for (int p = 0; p < 4; p++) {
        int c0i = coBase + 2 * p;
        float blo = (c0i     < A.cOut) ? bB[c0i]     : 0.f;
        float bhi = (c0i + 1 < A.cOut) ? bB[c0i + 1] : 0.f;
        u64 bp = packf(blo, bhi);
#pragma unroll
        for (int jj = 0; jj < 4; jj++) acc[p][jj] = bp;
    }

    long long HW = (long long)H * W;

    for (int c0 = 0; c0 < 256; c0 += CI_CH) {
        // stage input halo tile (zero-padded SAME borders)
        for (int idx = tid; idx < CI_CH * 180; idx += THREADS) {
            int ci  = idx / 180;
            int rem = idx - ci * 180;
            int r   = rem / 18;
            int c   = rem - r * 18;
            int gy = y0 - 1 + r;
            int gx = x0 - 1 + c;
            float v = 0.f;
            if ((unsigned)gy < (unsigned)H && (unsigned)gx < (unsigned)W)
                v = inB[(long long)(c0 + ci) * HW + (long long)gy * W + gx];
            in_s[(ci * 10 + r) * 19 + c] = v;
        }
        // stage weights, transposed to [ci][tap][co] (conflict-free stores: co fastest)
        for (int idx = tid; idx < CI_CH * 9 * CO_T; idx += THREADS) {
            int co = idx & 63;
            int k  = idx >> 6;                   // k = ci*9 + tap, 0..71
            int gco = cb * CO_T + co;
            float v = 0.f;
            if (gco < A.cOut)
                v = wB[(long long)gco * 2304 + c0 * 9 + k];
            w_s[k * 64 + co] = v;
        }
        __syncthreads();

#pragma unroll 2
        for (int ci = 0; ci < CI_CH; ci++) {
#pragma unroll
            for (int kh = 0; kh < 3; kh++) {
                const float* irow = &in_s[(ci * 10 + rL + kh) * 19 + cL];
                u64 d[6];
#pragma unroll
                for (int j = 0; j < 6; j++) d[j] = dupf(irow[j]);
#pragma unroll
                for (int kw = 0; kw < 3; kw++) {
                    const u64* wp = (const u64*)&w_s[(ci * 9 + kh * 3 + kw) * 64 + tyg * 8];
                    u64 w0 = wp[0], w1 = wp[1], w2 = wp[2], w3 = wp[3];  // broadcast LDS
#pragma unroll
                    for (int jj = 0; jj < 4; jj++) {
                        u64 dv = d[kw + jj];
                        fma2(acc[0][jj], w0, dv);
                        fma2(acc[1][jj], w1, dv);
                        fma2(acc[2][jj], w2, dv);
                        fma2(acc[3][jj], w3, dv);
                    }
                }
            }
        }
        __syncthreads();
    }

    if (!colOk) return;

    if (MAIN) {
        // bias + ReLU, NCHW into activation buffer
        float* outB = A.outP[head] + (long long)n * ACT_NSTR + A.outOff[s];
#pragma unroll
        for (int p = 0; p < 4; p++) {
            float lo[4], hi[4];
#pragma unroll
            for (int jj = 0; jj < 4; jj++) unpackf(acc[p][jj], lo[jj], hi[jj]);
            int co = coBase + 2 * p;
            float4 o0 = make_float4(fmaxf(lo[0], 0.f), fmaxf(lo[1], 0.f),
                                    fmaxf(lo[2], 0.f), fmaxf(lo[3], 0.f));
            float4 o1 = make_float4(fmaxf(hi[0], 0.f), fmaxf(hi[1], 0.f),
                                    fmaxf(hi[2], 0.f), fmaxf(hi[3], 0.f));
            *(float4*)&outB[((long long)co       * H + y) * W + x] = o0;
            *(float4*)&outB[((long long)(co + 1) * H + y) * W + x] = o1;
        }
    } else {
        // bias only, permuted scatter: out[n][base_s + (y*W+x)*9 + a][c], co = a*kk + c
        float* outB = A.outP[0];
        long long posRow = A.outOff[s] + ((long long)y * W + x) * 9;
#pragma unroll
        for (int p = 0; p < 4; p++) {
            float vv[2][4];
#pragma unroll
            for (int jj = 0; jj < 4; jj++) unpackf(acc[p][jj], vv[0][jj], vv[1][jj]);
#pragma unroll
            for (int h2 = 0; h2 < 2; h2++) {
                int co = coBase + 2 * p + h2;
                if (co < A.cOut) {
                    int a = co / A.kk;
                    int c = co - a * A.kk;
#pragma unroll
                    for (int jj = 0; jj < 4; jj++) {
                        long long idx = (n * ANCH_TOT + posRow + jj * 9 + a) * (long long)A.kk + c;
                        outB[idx] = vv[h2][jj];
                    }
                }
            }
        }
    }
}

extern "C" void kernel_launch(void* const* d_in, const int* in_sizes, int n_in,
                              void* d_out, int out_size)
{
    (void)in_sizes; (void)out_size;
    if (n_in < 13) return;

    const float* feat[5];
    for (int i = 0; i < 5; i++) feat[i] = (const float*)d_in[i];
    const float* cls_conv_w = (const float*)d_in[5];
    const float* cls_conv_b = (const float*)d_in[6];
    const float* cls_out_w  = (const float*)d_in[7];
    const float* cls_out_b  = (const float*)d_in[8];
    const float* reg_conv_w = (const float*)d_in[9];
    const float* reg_conv_b = (const float*)d_in[10];
    const float* reg_out_w  = (const float*)d_in[11];
    const float* reg_out_b  = (const float*)d_in[12];

    float *actA = nullptr, *actB = nullptr;
    cudaGetSymbolAddress((void**)&actA, g_actA);
    cudaGetSymbolAddress((void**)&actB, g_actB);

    static const int Hs[5]  = {128, 64, 32, 16, 8};
    static const int tXs[5] = {8, 4, 2, 1, 1};
    static const int tSt[6] = {0, 128, 160, 168, 170, 171};
    static const long long actOff[5] = {0, 4194304, 5242880, 5505024, 5570560};
    static const long long posOff[5] = {0, 147456, 184320, 193536, 195840};

    auto fillMeta = [&](KArgs& a) {
        for (int s = 0; s < 5; s++) { a.Hs[s] = Hs[s]; a.Ws[s] = Hs[s]; a.tXs[s] = tXs[s]; }
        for (int s = 0; s < 6; s++) a.tStart[s] = tSt[s];
    };

    // ---- layer 0: feats -> actA (both heads fused in grid.z) ----
    {
        KArgs a{}; fillMeta(a);
        for (int s = 0; s < 5; s++) {
            a.inP[s]     = feat[s];
            a.inP[5 + s] = feat[s];
            a.inNStr[s]  = 256LL * Hs[s] * Hs[s];
            a.outOff[s]  = actOff[s];
        }
        a.wP[0] = cls_conv_w;  a.wP[1] = reg_conv_w;
        a.bP[0] = cls_conv_b;  a.bP[1] = reg_conv_b;
        a.outP[0] = actA;      a.outP[1] = actA + ACT_N;
        a.cOut = 256; a.kk = 1;
        conv3x3_k<1><<<dim3(171, 4, 4), THREADS>>>(a);
    }

    // ---- layers 1..3: ping-pong ----
    float* src = actA;
    float* dst = actB;
    for (int l = 1; l < 4; l++) {
        KArgs a{}; fillMeta(a);
        for (int s = 0; s < 5; s++) {
            a.inP[s]     = src + actOff[s];
            a.inP[5 + s] = src + ACT_N + actOff[s];
            a.inNStr[s]  = ACT_NSTR;
            a.outOff[s]  = actOff[s];
        }
        a.wP[0] = cls_conv_w + (long long)l * 589824;
        a.wP[1] = reg_conv_w + (long long)l * 589824;
        a.bP[0] = cls_conv_b + l * 256;
        a.bP[1] = reg_conv_b + l * 256;
        a.outP[0] = dst; a.outP[1] = dst + ACT_N;
        a.cOut = 256; a.kk = 1;
        conv3x3_k<1><<<dim3(171, 4, 4), THREADS>>>(a);
        float* t = src; src = dst; dst = t;
    }
    // after 4 layers, final trunk activations live in `src` (== actB)

    // ---- cls output conv: 256 -> 819, permuted scatter into d_out[0 ..) ----
    {
        KArgs a{}; fillMeta(a);
        for (int s = 0; s < 5; s++) {
            a.inP[s]    = src + actOff[s];
            a.inNStr[s] = ACT_NSTR;
            a.outOff[s] = posOff[s];
        }
        a.wP[0] = cls_out_w; a.bP[0] = cls_out_b;
        a.outP[0] = (float*)d_out;
        a.cOut = 819; a.kk = 91;
        conv3x3_k<0><<<dim3(171, 13, 2), THREADS>>>(a);
    }

    // ---- reg output conv: 256 -> 36, permuted scatter after cls block ----
    {
        KArgs a{}; fillMeta(a);
        for (int s = 0; s < 5; s++) {
            a.inP[s]    = src + ACT_N + actOff[s];
            a.inNStr[s] = ACT_NSTR;
            a.outOff[s] = posOff[s];
        }
        a.wP[0] = reg_out_w; a.bP[0] = reg_out_b;
        a.outP[0] = (float*)d_out + 35747712LL;   // 2 * 196416 * 91
        a.cOut = 36; a.kk = 4;
        conv3x3_k<0><<<dim3(171, 1, 2), THREADS>>>(a);
    }
}

// round 6
// speedup vs baseline: 1.0597x; 1.0597x over previous
#include <cuda_runtime.h>

typedef unsigned long long u64;

#define NSC 5
#define CO_T 64
#define CI_CH 8
#define THREADS 256
#define ISTR 20              // input smem row stride (words); rL*20 mod 32 tiles banks
#define ACT_NSTR 5586944LL   // per-n elements in activation buffer (256 * 21824)
#define ACT_N    11173888LL  // per-head elements (n = 2)
#define ANCH_TOT 196416LL    // sum(H*W*9)

// Ping-pong activation scratch: [head][n*ACT_NSTR + scale_off + c*H*W + y*W + x]
__device__ float g_actA[2][11173888];
__device__ float g_actB[2][11173888];

struct KArgs {
    const float* inP[10];        // [head*5 + scale], base for n=0
    const float* wP[2];          // per-head weights [Cout][256][3][3]
    const float* bP[2];          // per-head bias
    float*       outP[2];        // MAIN: per-head act base; else: d_out region
    long long    inNStr[NSC];    // per-scale n-stride (elements)
    long long    outOff[NSC];    // MAIN: act scale offsets; else: anchor-position base per scale
    int Hs[NSC], Ws[NSC], tXs[NSC];
    int tStart[NSC + 1];
    int cOut;                    // 256 / 819 / 36
    int kk;                      // classes-per-anchor (91 / 4); unused in MAIN
};

__device__ __forceinline__ u64 dupf(float x) {
    u64 r; asm("mov.b64 %0, {%1, %1};" : "=l"(r) : "f"(x)); return r;
}
__device__ __forceinline__ u64 packf(float lo, float hi) {
    u64 r; asm("mov.b64 %0, {%1, %2};" : "=l"(r) : "f"(lo), "f"(hi)); return r;
}
__device__ __forceinline__ void unpackf(u64 v, float& lo, float& hi) {
    asm("mov.b64 {%0, %1}, %2;" : "=f"(lo), "=f"(hi) : "l"(v));
}
// packed dual-FMA: 2 fp32 FMAs per instruction (sm_100+)
__device__ __forceinline__ void fma2(u64& a, u64 w, u64 x) {
    asm("fma.rn.f32x2 %0, %1, %2, %0;" : "+l"(a) : "l"(w), "l"(x));
}

// One block: 64 output channels x (8 rows x 16 cols) spatial tile.
// Thread tile: 8 co (4 f32x2 pairs) x 4 consecutive cols.
// Lane map: rL = lane&7 (row), cg = lane>>3 (col group) -> conflict-free
// vectorized LDS with row stride 20.
// K-loop: 32 chunks of 8 input channels staged through shared memory.
template<int MAIN>
__global__ __launch_bounds__(THREADS, 2)
void conv3x3_k(KArgs A)
{
    __shared__ __align__(16) float in_s[CI_CH * 10 * ISTR];  // halo 10x18, stride 20
    __shared__ __align__(16) float w_s[CI_CH * 9 * CO_T];    // [ci][tap][co]

    // scale lookup from linear spatial-tile id
    int bt = blockIdx.x;
    int s = 0;
#pragma unroll
    for (int i = 1; i < NSC; i++) if (bt >= A.tStart[i]) s = i;
    int local = bt - A.tStart[s];
    int H = A.Hs[s], W = A.Ws[s], tX = A.tXs[s];
    int tileX = local % tX, tileY = local / tX;

    int z = blockIdx.z;
    int head = MAIN ? (z >> 1) : 0;
    int n    = MAIN ? (z & 1)  : z;
    int cb   = blockIdx.y;

    const float* inB = A.inP[head * NSC + s] + (long long)n * A.inNStr[s];
    const float* wB  = A.wP[head];
    const float* bB  = A.bP[head];

    int tid = threadIdx.x;
    int spg = tid & 31, tyg = tid >> 5;          // warp = 32 spatial groups, fixed co-group
    int rL  = spg & 7, cg = spg >> 3, cL = cg * 4;
    int y0 = tileY * 8, x0 = tileX * 16;
    int y = y0 + rL, x = x0 + cL;
    bool colOk = (x < W);                        // W multiple of 4; all-or-nothing per 4-col group
    int coBase = cb * CO_T + tyg * 8;

    u64 acc[4][4];
#pragma unroll
    for (int p = 0; p < 4; p++) {
        int c0i = coBase + 2 * p;
        float blo = (c0i     < A.cOut) ? bB[c0i]     : 0.f;
        float bhi = (c0i + 1 < A.cOut) ? bB[c0i + 1] : 0.f;
        u64 bp = packf(blo, bhi);
#pragma unroll
        for (int jj = 0; jj < 4; jj++) acc[p][jj] = bp;
    }

    long long HW = (long long)H * W;

    for (int c0 = 0; c0 < 256; c0 += CI_CH) {
        // stage input halo tile (zero-padded SAME borders), stride-20 rows
        for (int idx = tid; idx < CI_CH * 180; idx += THREADS) {
            int ci  = idx / 180;
            int rem = idx - ci * 180;
            int r   = rem / 18;
            int c   = rem - r * 18;
            int gy = y0 - 1 + r;
            int gx = x0 - 1 + c;
            float v = 0.f;
            if ((unsigned)gy < (unsigned)H && (unsigned)gx < (unsigned)W)
                v = inB[(long long)(c0 + ci) * HW + (long long)gy * W + gx];
            in_s[(ci * 10 + r) * ISTR + c] = v;
        }
        // stage weights, transposed to [ci][tap][co] (conflict-free stores: co fastest)
        for (int idx = tid; idx < CI_CH * 9 * CO_T; idx += THREADS) {
            int co = idx & 63;
            int k  = idx >> 6;                   // k = ci*9 + tap, 0..71
            int gco = cb * CO_T + co;
            float v = 0.f;
            if (gco < A.cOut)
                v = wB[(long long)gco * 2304 + c0 * 9 + k];
            w_s[k * 64 + co] = v;
        }
        __syncthreads();

#pragma unroll 2
        for (int ci = 0; ci < CI_CH; ci++) {
#pragma unroll
            for (int kh = 0; kh < 3; kh++) {
                const float* irow = &in_s[(ci * 10 + rL + kh) * ISTR + cL];
                float4 fa = *(const float4*)irow;             // LDS.128, conflict-free
                float2 fb = *(const float2*)(irow + 4);       // LDS.64, conflict-free
                u64 d[6];
                d[0] = dupf(fa.x); d[1] = dupf(fa.y);
                d[2] = dupf(fa.z); d[3] = dupf(fa.w);
                d[4] = dupf(fb.x); d[5] = dupf(fb.y);
#pragma unroll
                for (int kw = 0; kw < 3; kw++) {
                    const ulonglong2* wq =
                        (const ulonglong2*)&w_s[(ci * 9 + kh * 3 + kw) * 64 + tyg * 8];
                    ulonglong2 wA = wq[0];                    // LDS.128 broadcast
                    ulonglong2 wC = wq[1];                    // LDS.128 broadcast
#pragma unroll
                    for (int jj = 0; jj < 4; jj++) {
                        u64 dv = d[kw + jj];
                        fma2(acc[0][jj], wA.x, dv);
                        fma2(acc[1][jj], wA.y, dv);
                        fma2(acc[2][jj], wC.x, dv);
                        fma2(acc[3][jj], wC.y, dv);
                    }
                }
            }
        }
        __syncthreads();
    }

    if (!colOk) return;

    if (MAIN) {
        // bias + ReLU, NCHW into activation buffer
        float* outB = A.outP[head] + (long long)n * ACT_NSTR + A.outOff[s];
#pragma unroll
        for (int p = 0; p < 4; p++) {
            float lo[4], hi[4];
#pragma unroll
            for (int jj = 0; jj < 4; jj++) unpackf(acc[p][jj], lo[jj], hi[jj]);
            int co = coBase + 2 * p;
            float4 o0 = make_float4(fmaxf(lo[0], 0.f), fmaxf(lo[1], 0.f),
                                    fmaxf(lo[2], 0.f), fmaxf(lo[3], 0.f));
            float4 o1 = make_float4(fmaxf(hi[0], 0.f), fmaxf(hi[1], 0.f),
                                    fmaxf(hi[2], 0.f), fmaxf(hi[3], 0.f));
            *(float4*)&outB[((long long)co       * H + y) * W + x] = o0;
            *(float4*)&outB[((long long)(co + 1) * H + y) * W + x] = o1;
        }
    } else {
        // bias only, permuted scatter: out[n][base_s + (y*W+x)*9 + a][c], co = a*kk + c
        float* outB = A.outP[0];
        long long posRow = A.outOff[s] + ((long long)y * W + x) * 9;
#pragma unroll
        for (int p = 0; p < 4; p++) {
            float vv[2][4];
#pragma unroll
            for (int jj = 0; jj < 4; jj++) unpackf(acc[p][jj], vv[0][jj], vv[1][jj]);
#pragma unroll
            for (int h2 = 0; h2 < 2; h2++) {
                int co = coBase + 2 * p + h2;
                if (co < A.cOut) {
                    int a = co / A.kk;
                    int c = co - a * A.kk;
#pragma unroll
                    for (int jj = 0; jj < 4; jj++) {
                        long long idx = (n * ANCH_TOT + posRow + jj * 9 + a) * (long long)A.kk + c;
                        outB[idx] = vv[h2][jj];
                    }
                }
            }
        }
    }
}

extern "C" void kernel_launch(void* const* d_in, const int* in_sizes, int n_in,
                              void* d_out, int out_size)
{
    (void)in_sizes; (void)out_size;
    if (n_in < 13) return;

    const float* feat[5];
    for (int i = 0; i < 5; i++) feat[i] = (const float*)d_in[i];
    const float* cls_conv_w = (const float*)d_in[5];
    const float* cls_conv_b = (const float*)d_in[6];
    const float* cls_out_w  = (const float*)d_in[7];
    const float* cls_out_b  = (const float*)d_in[8];
    const float* reg_conv_w = (const float*)d_in[9];
    const float* reg_conv_b = (const float*)d_in[10];
    const float* reg_out_w  = (const float*)d_in[11];
    const float* reg_out_b  = (const float*)d_in[12];

    float *actA = nullptr, *actB = nullptr;
    cudaGetSymbolAddress((void**)&actA, g_actA);
    cudaGetSymbolAddress((void**)&actB, g_actB);

    static const int Hs[5]  = {128, 64, 32, 16, 8};
    static const int tXs[5] = {8, 4, 2, 1, 1};
    static const int tSt[6] = {0, 128, 160, 168, 170, 171};
    static const long long actOff[5] = {0, 4194304, 5242880, 5505024, 5570560};
    static const long long posOff[5] = {0, 147456, 184320, 193536, 195840};

    auto fillMeta = [&](KArgs& a) {
        for (int s = 0; s < 5; s++) { a.Hs[s] = Hs[s]; a.Ws[s] = Hs[s]; a.tXs[s] = tXs[s]; }
        for (int s = 0; s < 6; s++) a.tStart[s] = tSt[s];
    };

    // ---- layer 0: feats -> actA (both heads fused in grid.z) ----
    {
        KArgs a{}; fillMeta(a);
        for (int s = 0; s < 5; s++) {
            a.inP[s]     = feat[s];
            a.inP[5 + s] = feat[s];
            a.inNStr[s]  = 256LL * Hs[s] * Hs[s];
            a.outOff[s]  = actOff[s];
        }
        a.wP[0] = cls_conv_w;  a.wP[1] = reg_conv_w;
        a.bP[0] = cls_conv_b;  a.bP[1] = reg_conv_b;
        a.outP[0] = actA;      a.outP[1] = actA + ACT_N;
        a.cOut = 256; a.kk = 1;
        conv3x3_k<1><<<dim3(171, 4, 4), THREADS>>>(a);
    }

    // ---- layers 1..3: ping-pong ----
    float* src = actA;
    float* dst = actB;
    for (int l = 1; l < 4; l++) {
        KArgs a{}; fillMeta(a);
        for (int s = 0; s < 5; s++) {
            a.inP[s]     = src + actOff[s];
            a.inP[5 + s] = src + ACT_N + actOff[s];
            a.inNStr[s]  = ACT_NSTR;
            a.outOff[s]  = actOff[s];
        }
        a.wP[0] = cls_conv_w + (long long)l * 589824;
        a.wP[1] = reg_conv_w + (long long)l * 589824;
        a.bP[0] = cls_conv_b + l * 256;
        a.bP[1] = reg_conv_b + l * 256;
        a.outP[0] = dst; a.outP[1] = dst + ACT_N;
        a.cOut = 256; a.kk = 1;
        conv3x3_k<1><<<dim3(171, 4, 4), THREADS>>>(a);
        float* t = src; src = dst; dst = t;
    }
    // after 4 layers, final trunk activations live in `src` (== actB)

    // ---- cls output conv: 256 -> 819, permuted scatter into d_out[0 ..) ----
    {
        KArgs a{}; fillMeta(a);
        for (int s = 0; s < 5; s++) {
            a.inP[s]    = src + actOff[s];
            a.inNStr[s] = ACT_NSTR;
            a.outOff[s] = posOff[s];
        }
        a.wP[0] = cls_out_w; a.bP[0] = cls_out_b;
        a.outP[0] = (float*)d_out;
        a.cOut = 819; a.kk = 91;
        conv3x3_k<0><<<dim3(171, 13, 2), THREADS>>>(a);
    }

    // ---- reg output conv: 256 -> 36, permuted scatter after cls block ----
    {
        KArgs a{}; fillMeta(a);
        for (int s = 0; s < 5; s++) {
            a.inP[s]    = src + ACT_N + actOff[s];
            a.inNStr[s] = ACT_NSTR;
            a.outOff[s] = posOff[s];
        }
        a.wP[0] = reg_out_w; a.bP[0] = reg_out_b;
        a.outP[0] = (float*)d_out + 35747712LL;   // 2 * 196416 * 91
        a.cOut = 36; a.kk = 4;
        conv3x3_k<0><<<dim3(171, 1, 2), THREADS>>>(a);
    }
}

// round 10
// speedup vs baseline: 3.2126x; 3.0315x over previous
#include <cuda_runtime.h>
#include <cuda_bf16.h>
#include <cstdint>

typedef unsigned int u32;
typedef unsigned long long u64;

#define THREADS 256
#define POS_TOT 21824
#define ANCH_TOT 196416LL

// ---------------- device scratch (no allocs) ----------------
// feats split: [n][pos][ci] bf16 planes (head-shared)
__device__ __align__(256) __nv_bfloat16 g_fHi[11173888], g_fLo[11173888];
// act ping-pong planes per head: [head][n*POS_TOT*256]
__device__ __align__(256) __nv_bfloat16 g_aHiA[2][11173888], g_aLoA[2][11173888];
__device__ __align__(256) __nv_bfloat16 g_aHiB[2][11173888], g_aLoB[2][11173888];
// weights split, layout [region][tap][co][ci]
__device__ __align__(256) __nv_bfloat16 g_wHi[6688512], g_wLo[6688512];

// ---------------- helpers ----------------
__device__ __forceinline__ u32 smem_u32(const void* p) {
    u32 a; asm("{ .reg .u64 t; cvta.to.shared.u64 t, %1; cvt.u32.u64 %0, t; }" : "=r"(a) : "l"(p));
    return a;
}
__device__ __forceinline__ void cp16(u32 saddr, const void* g, bool pred) {
    int sz = pred ? 16 : 0;
    asm volatile("cp.async.cg.shared.global [%0], [%1], 16, %2;"
                 :: "r"(saddr), "l"(g), "r"(sz) : "memory");
}
__device__ __forceinline__ u32 swz(u32 off) { return off ^ ((off >> 3) & 0x70); }

__device__ __forceinline__ void ldm4(u32* r, u32 addr) {
    asm volatile("ldmatrix.sync.aligned.m8n8.x4.shared.b16 {%0,%1,%2,%3}, [%4];"
                 : "=r"(r[0]), "=r"(r[1]), "=r"(r[2]), "=r"(r[3]) : "r"(addr) : "memory");
}
__device__ __forceinline__ void mma16816(float* c, const u32* a, const u32* b) {
    asm volatile(
        "mma.sync.aligned.m16n8k16.row.col.f32.bf16.bf16.f32 "
        "{%0,%1,%2,%3}, {%4,%5,%6,%7}, {%8,%9}, {%0,%1,%2,%3};"
        : "+f"(c[0]), "+f"(c[1]), "+f"(c[2]), "+f"(c[3])
        : "r"(a[0]), "r"(a[1]), "r"(a[2]), "r"(a[3]), "r"(b[0]), "r"(b[1]));
}

// ---------------- prologue: split weights ----------------
// src [Co][256][9] fp32 -> dst [9][Co][256] bf16 hi/lo
__global__ void split_w_k(const float* __restrict__ src, __nv_bfloat16* hi, __nv_bfloat16* lo, int Co) {
    int total = 9 * Co * 256;
    for (int i = blockIdx.x * blockDim.x + threadIdx.x; i < total; i += gridDim.x * blockDim.x) {
        int tap = i / (Co * 256);
        int rem = i - tap * (Co * 256);
        int co = rem >> 8, ci = rem & 255;
        float v = src[(co * 256 + ci) * 9 + tap];
        __nv_bfloat16 h = __float2bfloat16(v);
        __nv_bfloat16 l = __float2bfloat16(v - __bfloat162float(h));
        hi[i] = h; lo[i] = l;
    }
}

// ---------------- prologue: split feats NCHW -> [n][pos][ci] ----------------
__global__ void split_f_k(const float* f0, const float* f1, const float* f2,
                          const float* f3, const float* f4,
                          __nv_bfloat16* hi, __nv_bfloat16* lo) {
    const int pb[6] = {0, 16384, 20480, 21504, 21760, 21824};
    const int Hs[5] = {128, 64, 32, 16, 8};
    const float* fp[5] = {f0, f1, f2, f3, f4};
    long long total = 2LL * POS_TOT * 256;
    for (long long i = (long long)blockIdx.x * blockDim.x + threadIdx.x; i < total;
         i += (long long)gridDim.x * blockDim.x) {
        int n = (int)(i / (POS_TOT * 256LL));
        int r = (int)(i - (long long)n * POS_TOT * 256);
        int pos = r >> 8, ci = r & 255;
        int s = 0;
        for (int k = 1; k < 5; k++) if (pos >= pb[k]) s = k;
        int p = pos - pb[s];
        int HW = Hs[s] * Hs[s];
        float v = fp[s][((long long)n * 256 + ci) * HW + p];
        __nv_bfloat16 h = __float2bfloat16(v);
        __nv_bfloat16 l = __float2bfloat16(v - __bfloat162float(h));
        hi[i] = h; lo[i] = l;
    }
}

// ---------------- main tensor-core conv (warp mma.sync) ----------------
struct CArgs {
    const __nv_bfloat16 *aHi[2], *aLo[2];   // per-head act planes (base, n=0)
    const __nv_bfloat16 *wHi[2], *wLo[2];   // per-head weight region [tap][co][ci]
    const float* bias[2];
    __nv_bfloat16 *oHi[2], *oLo[2];         // MAIN output planes
    float* outP;                            // OUT output
    int cOut, kk;
};

// Block: M=128 pos (8x16 spatial tile) x N=128 co. 8 warps, each 32M x 64N.
// 36 stages (9 taps x 4 ci-chunks of 64), 64KB/stage double buffered.
template<int MAIN>
__global__ __launch_bounds__(THREADS, 1) void conv_tc(CArgs A)
{
    extern __shared__ __align__(16) char dsm_raw[];

    const int tid = threadIdx.x, wid = tid >> 5, lane = tid & 31;

    const int Hs[5]  = {128, 64, 32, 16, 8};
    const int tXs[5] = {8, 4, 2, 1, 1};
    const int tSt[5] = {0, 128, 160, 168, 170};
    const int posG[5] = {0, 16384, 20480, 21504, 21760};
    const long long posO9[5] = {0, 147456, 184320, 193536, 195840};

    int bt = blockIdx.x;
    int s = 0;
#pragma unroll
    for (int i = 1; i < 5; i++) if (bt >= tSt[i]) s = i;
    int local = bt - tSt[s];
    int H = Hs[s], W = H, tX = tXs[s];
    int y0 = (local / tX) * 8, x0 = (local % tX) * 16;
    int cb = blockIdx.y;
    int z  = blockIdx.z;
    int head = MAIN ? (z >> 1) : 0;
    int n    = MAIN ? (z & 1)  : z;

    const __nv_bfloat16* aHi = A.aHi[head];
    const __nv_bfloat16* aLo = A.aLo[head];
    const __nv_bfloat16* wHi = A.wHi[head];
    const __nv_bfloat16* wLo = A.wLo[head];

    u32 smem0 = (smem_u32(dsm_raw) + 1023u) & ~1023u;

    long long posBaseG = (long long)n * POS_TOT + posG[s];

    // per-thread staging geometry (4 chunks of 16B per 16KB plane)
    int pr_[4], pc_[4], co_[4], c16e_[4];
    u32 swo_[4];
    bool okB_[4];
#pragma unroll
    for (int q = 0; q < 4; q++) {
        int ch = tid * 4 + q;            // 0..1023
        int row = ch >> 3, c16 = ch & 7;
        pr_[q] = row >> 4; pc_[q] = row & 15;
        c16e_[q] = c16 * 8;
        swo_[q] = swz((u32)(row * 128 + c16 * 16));
        co_[q] = cb * 128 + row;
        okB_[q] = co_[q] < A.cOut;
    }

    auto issue = [&](int it) {
        int buf = it & 1;
        int tap = it >> 2, kcq = it & 3;
        int dy = tap / 3 - 1, dx = tap % 3 - 1;
        int cic = kcq * 64;
        u32 base = smem0 + buf * 65536;
        long long wStageBase = ((long long)tap * A.cOut) * 256 + cic;
#pragma unroll
        for (int q = 0; q < 4; q++) {
            int gy = y0 + pr_[q] + dy, gx = x0 + pc_[q] + dx;
            bool ok = ((unsigned)gy < (unsigned)H) && ((unsigned)gx < (unsigned)W);
            long long e = (posBaseG + (long long)gy * W + gx) * 256 + cic + c16e_[q];
            cp16(base + swo_[q],         aHi + e, ok);
            cp16(base + 16384 + swo_[q], aLo + e, ok);
            long long ew = wStageBase + (long long)co_[q] * 256 + c16e_[q];
            cp16(base + 32768 + swo_[q], wHi + ew, okB_[q]);
            cp16(base + 49152 + swo_[q], wLo + ew, okB_[q]);
        }
        asm volatile("cp.async.commit_group;" ::: "memory");
    };

    // warp tile
    const int mBase = (wid & 3) * 32;
    const int nBase = (wid >> 2) * 64;
    // ldmatrix lane-derived offsets
    const int aTile  = lane >> 3;
    const int aRowOf = ((aTile & 1) << 3) + (lane & 7);
    const int aKg    = aTile >> 1;
    const int bRowOf = (((lane >> 4) & 1) << 3) + (lane & 7);
    const int bKg    = (lane >> 3) & 1;

    float acc[2][8][4];
#pragma unroll
    for (int mt = 0; mt < 2; mt++)
#pragma unroll
        for (int nt = 0; nt < 8; nt++)
#pragma unroll
            for (int j = 0; j < 4; j++) acc[mt][nt][j] = 0.f;

    issue(0);

    for (int it = 0; it < 36; ++it) {
        if (it < 35) {
            issue(it + 1);
            asm volatile("cp.async.wait_group 1;" ::: "memory");
        } else {
            asm volatile("cp.async.wait_group 0;" ::: "memory");
        }
        __syncthreads();

        u32 base = smem0 + (it & 1) * 65536;
#pragma unroll
        for (int k16 = 0; k16 < 4; k16++) {
            int kg0 = k16 * 2;
            u32 ah[2][4], al[2][4];
#pragma unroll
            for (int mt = 0; mt < 2; mt++) {
                u32 off = swz((u32)((mBase + mt * 16 + aRowOf) * 128 + (kg0 + aKg) * 16));
                ldm4(ah[mt], base + off);
                ldm4(al[mt], base + 16384 + off);
            }
#pragma unroll
            for (int nt = 0; nt < 4; nt++) {
                u32 off = swz((u32)((nBase + nt * 16 + bRowOf) * 128 + (kg0 + bKg) * 16));
                u32 bh[4], bl[4];
                ldm4(bh, base + 32768 + off);
                ldm4(bl, base + 49152 + off);
#pragma unroll
                for (int mt = 0; mt < 2; mt++) {
                    mma16816(acc[mt][nt * 2],     ah[mt], &bh[0]);
                    mma16816(acc[mt][nt * 2],     al[mt], &bh[0]);
                    mma16816(acc[mt][nt * 2],     ah[mt], &bl[0]);
                    mma16816(acc[mt][nt * 2 + 1], ah[mt], &bh[2]);
                    mma16816(acc[mt][nt * 2 + 1], al[mt], &bh[2]);
                    mma16816(acc[mt][nt * 2 + 1], ah[mt], &bl[2]);
                }
            }
        }
        __syncthreads();
    }

    // ---------------- epilogue from register accumulators ----------------
    const float* bb = A.bias[head];
    int rQ = lane >> 2;               // row within m16 (0..7)
    int cQ = (lane & 3) * 2;          // col pair within n8

#pragma unroll
    for (int mt = 0; mt < 2; mt++) {
#pragma unroll
        for (int nt = 0; nt < 8; nt++) {
            // FIX (R9): global output channel must include the block's channel
            // tile offset cb*128. Previously co0 lacked it -> only co 0..127
            // ever written (rel_err = sqrt(1-128/819) = 0.91852, as observed).
            int co0 = cb * 128 + nBase + nt * 8 + cQ;
#pragma unroll
            for (int half = 0; half < 2; half++) {
                int row = mBase + mt * 16 + rQ + half * 8;
                int pr = row >> 4, pc = row & 15;
                int y = y0 + pr, x = x0 + pc;
                if (x >= W) continue;
                float v0 = acc[mt][nt][half * 2];
                float v1 = acc[mt][nt][half * 2 + 1];
                if (MAIN) {
                    v0 = fmaxf(v0 + bb[co0], 0.f);
                    v1 = fmaxf(v1 + bb[co0 + 1], 0.f);
                    __nv_bfloat16 h0 = __float2bfloat16(v0);
                    __nv_bfloat16 h1 = __float2bfloat16(v1);
                    __nv_bfloat16 l0 = __float2bfloat16(v0 - __bfloat162float(h0));
                    __nv_bfloat16 l1 = __float2bfloat16(v1 - __bfloat162float(h1));
                    u32 hw = (u32)__bfloat16_as_ushort(h0) | ((u32)__bfloat16_as_ushort(h1) << 16);
                    u32 lw = (u32)__bfloat16_as_ushort(l0) | ((u32)__bfloat16_as_ushort(l1) << 16);
                    long long ob = (posBaseG + (long long)y * W + x) * 256 + co0;
                    *(u32*)(A.oHi[head] + ob) = hw;
                    *(u32*)(A.oLo[head] + ob) = lw;
                } else {
                    long long rowB = (long long)n * ANCH_TOT + posO9[s] + (long long)(y * W + x) * 9;
#pragma unroll
                    for (int e = 0; e < 2; e++) {
                        int co = co0 + e;
                        if (co < A.cOut) {
                            float v = (e ? v1 : v0) + bb[co];
                            int a = co / A.kk, c = co - a * A.kk;
                            A.outP[(rowB + a) * (long long)A.kk + c] = v;
                        }
                    }
                }
            }
        }
    }
}

// ---------------- host ----------------
extern "C" void kernel_launch(void* const* d_in, const int* in_sizes, int n_in,
                              void* d_out, int out_size)
{
    (void)in_sizes; (void)out_size;
    if (n_in < 13) return;

    const float* feat[5];
    for (int i = 0; i < 5; i++) feat[i] = (const float*)d_in[i];
    const float* cls_conv_w = (const float*)d_in[5];
    const float* cls_conv_b = (const float*)d_in[6];
    const float* cls_out_w  = (const float*)d_in[7];
    const float* cls_out_b  = (const float*)d_in[8];
    const float* reg_conv_w = (const float*)d_in[9];
    const float* reg_conv_b = (const float*)d_in[10];
    const float* reg_out_w  = (const float*)d_in[11];
    const float* reg_out_b  = (const float*)d_in[12];

    __nv_bfloat16 *fHi, *fLo, *wHi, *wLo;
    __nv_bfloat16 *aHiA, *aLoA, *aHiB, *aLoB;
    cudaGetSymbolAddress((void**)&fHi, g_fHi);
    cudaGetSymbolAddress((void**)&fLo, g_fLo);
    cudaGetSymbolAddress((void**)&wHi, g_wHi);
    cudaGetSymbolAddress((void**)&wLo, g_wLo);
    cudaGetSymbolAddress((void**)&aHiA, g_aHiA);
    cudaGetSymbolAddress((void**)&aLoA, g_aLoA);
    cudaGetSymbolAddress((void**)&aHiB, g_aHiB);
    cudaGetSymbolAddress((void**)&aLoB, g_aLoB);

    cudaFuncSetAttribute(conv_tc<1>, cudaFuncAttributeMaxDynamicSharedMemorySize, 132096);
    cudaFuncSetAttribute(conv_tc<0>, cudaFuncAttributeMaxDynamicSharedMemorySize, 132096);

    const long long PL = 11173888LL;     // plane elems per head
    const long long WTRUNK = 589824LL;   // 9*256*256

    // prologues
    split_f_k<<<4096, 256>>>(feat[0], feat[1], feat[2], feat[3], feat[4], fHi, fLo);
    for (int l = 0; l < 4; l++) {
        split_w_k<<<1024, 256>>>(cls_conv_w + l * 589824, wHi + l * WTRUNK, wLo + l * WTRUNK, 256);
        split_w_k<<<1024, 256>>>(reg_conv_w + l * 589824, wHi + (4 + l) * WTRUNK, wLo + (4 + l) * WTRUNK, 256);
    }
    split_w_k<<<2048, 256>>>(cls_out_w, wHi + 4718592, wLo + 4718592, 819);
    split_w_k<<<256, 256>>>(reg_out_w, wHi + 6605568, wLo + 6605568, 36);

    // trunk layers
    __nv_bfloat16 *srcHi = fHi, *srcLo = fLo;      // layer0: feats (head-shared)
    bool srcIsFeat = true;
    __nv_bfloat16 *pHi[2] = {aHiA, aHiB}, *pLo[2] = {aLoA, aLoB};
    int dstIdx = 0;
    for (int l = 0; l < 4; l++) {
        CArgs a{};
        for (int h = 0; h < 2; h++) {
            a.aHi[h] = srcIsFeat ? srcHi : srcHi + h * PL;
            a.aLo[h] = srcIsFeat ? srcLo : srcLo + h * PL;
            a.wHi[h] = wHi + (h * 4 + l) * WTRUNK;
            a.wLo[h] = wLo + (h * 4 + l) * WTRUNK;
            a.bias[h] = (h == 0 ? cls_conv_b : reg_conv_b) + l * 256;
            a.oHi[h] = pHi[dstIdx] + h * PL;
            a.oLo[h] = pLo[dstIdx] + h * PL;
        }
        a.cOut = 256; a.kk = 1;
        conv_tc<1><<<dim3(171, 2, 4), THREADS, 132096>>>(a);
        srcHi = pHi[dstIdx]; srcLo = pLo[dstIdx];
        srcIsFeat = false;
        dstIdx ^= 1;
    }

    // cls output conv (head0 trunk result)
    {
        CArgs a{};
        a.aHi[0] = srcHi; a.aLo[0] = srcLo;
        a.wHi[0] = wHi + 4718592; a.wLo[0] = wLo + 4718592;
        a.bias[0] = cls_out_b;
        a.outP = (float*)d_out;
        a.cOut = 819; a.kk = 91;
        conv_tc<0><<<dim3(171, 7, 2), THREADS, 132096>>>(a);
    }
    // reg output conv (head1 trunk result)
    {
        CArgs a{};
        a.aHi[0] = srcHi + PL; a.aLo[0] = srcLo + PL;
        a.wHi[0] = wHi + 6605568; a.wLo[0] = wLo + 6605568;
        a.bias[0] = reg_out_b;
        a.outP = (float*)d_out + 35747712LL;   // 2 * 196416 * 91
        a.cOut = 36; a.kk = 4;
        conv_tc<0><<<dim3(171, 1, 2), THREADS, 132096>>>(a);
    }
}